// round 2
// baseline (speedup 1.0000x reference)
#include <cuda_runtime.h>
#include <cuda_bf16.h>
#include <math.h>

#define NMAX 100000
#define EMAX 1600000

// Scratch (allocation-free rule: __device__ globals)
__device__ float g_support[(size_t)NMAX * 128];
__device__ float g_t[(size_t)NMAX * 128];
__device__ float g_sum[4][128];
__device__ float g_sq[4][128];
__device__ int   g_rowptr[NMAX + 1];

// ---------------------------------------------------------------------------
// Zero the BN stat accumulators (all 4 layers) once per launch.
__global__ void zero_stats_kernel() {
    int i = threadIdx.x;
    if (i < 128) {
        #pragma unroll
        for (int l = 0; l < 4; l++) { g_sum[l][i] = 0.f; g_sq[l][i] = 0.f; }
    }
}

// ---------------------------------------------------------------------------
// CSR row_ptr from sorted adj_row via binary search (lower_bound of r).
__global__ void rowptr_kernel(const int* __restrict__ adj_row, int N, int E) {
    int r = blockIdx.x * blockDim.x + threadIdx.x;
    if (r > N) return;
    int lo = 0, hi = E;
    while (lo < hi) {
        int mid = (lo + hi) >> 1;
        if (adj_row[mid] < r) lo = mid + 1; else hi = mid;
    }
    g_rowptr[r] = lo;
}

// ---------------------------------------------------------------------------
// Tiled fp32 SGEMM: C[N,OUT] = A[N,K] @ W[K,OUT]
// BM=64 rows/block, BK=32, 16x16 threads, each thread: 4 x (OUT/16) outputs.
template<int K, int OUT>
__global__ void gemm_kernel(const float* __restrict__ A, const float* __restrict__ W,
                            float* __restrict__ C, int N) {
    constexpr int BM = 64, BK = 32;
    constexpr int TM = 4;
    constexpr int TN = OUT / 16;           // 8, 8, 4, 2
    __shared__ float As[BK][BM];           // A tile, transposed
    __shared__ float Ws[BK][OUT];

    const int tx = threadIdx.x;            // 0..15 -> col groups
    const int ty = threadIdx.y;            // 0..15 -> row groups
    const int tid = ty * 16 + tx;
    const int row0 = blockIdx.x * BM;

    float acc[TM][TN];
    #pragma unroll
    for (int i = 0; i < TM; i++)
        #pragma unroll
        for (int j = 0; j < TN; j++) acc[i][j] = 0.f;

    for (int kb = 0; kb < K; kb += BK) {
        // Load A tile (transposed): 64x32 elems, coalesced over k
        #pragma unroll
        for (int p = 0; p < (BM * BK) / 256; p++) {
            int idx = p * 256 + tid;
            int r = idx / BK, k = idx % BK;
            int gr = row0 + r;
            float v = (gr < N) ? A[(size_t)gr * K + kb + k] : 0.f;
            As[k][r] = v;
        }
        // Load W tile: BKxOUT elems, coalesced over c
        #pragma unroll
        for (int p = 0; p < (BK * OUT) / 256; p++) {
            int idx = p * 256 + tid;
            int k = idx / OUT, c = idx % OUT;
            Ws[k][c] = W[(size_t)(kb + k) * OUT + c];
        }
        __syncthreads();

        #pragma unroll
        for (int k = 0; k < BK; k++) {
            float a[TM], w[TN];
            #pragma unroll
            for (int i = 0; i < TM; i++) a[i] = As[k][ty * TM + i];
            #pragma unroll
            for (int j = 0; j < TN; j++) w[j] = Ws[k][tx * TN + j];
            #pragma unroll
            for (int i = 0; i < TM; i++)
                #pragma unroll
                for (int j = 0; j < TN; j++)
                    acc[i][j] = fmaf(a[i], w[j], acc[i][j]);
        }
        __syncthreads();
    }

    #pragma unroll
    for (int i = 0; i < TM; i++) {
        int gr = row0 + ty * TM + i;
        if (gr < N) {
            float* crow = C + (size_t)gr * OUT + tx * TN;
            #pragma unroll
            for (int j = 0; j < TN; j++) crow[j] = acc[i][j];
        }
    }
}

// ---------------------------------------------------------------------------
// SpMM (warp per row, sorted rows / CSR ranges) + leaky_relu + elu fused,
// plus block-local BN stat accumulation (sum, sumsq per column).
template<int OUT, int LAYER>
__global__ void spmm_kernel(const float* __restrict__ support,
                            const int* __restrict__ col,
                            const float* __restrict__ vals,
                            float* __restrict__ t, int N) {
    constexpr int J = OUT / 32;
    __shared__ float ssum[OUT], ssq[OUT];
    const int tid = threadIdx.x;
    for (int i = tid; i < OUT; i += blockDim.x) { ssum[i] = 0.f; ssq[i] = 0.f; }
    __syncthreads();

    const int lane = tid & 31;
    const int warp = tid >> 5;
    const int row = blockIdx.x * 8 + warp;

    if (row < N) {
        float acc[J];
        #pragma unroll
        for (int j = 0; j < J; j++) acc[j] = 0.f;

        const int s = g_rowptr[row];
        const int e = g_rowptr[row + 1];
        for (int i = s; i < e; i++) {
            int c = __ldg(&col[i]);
            float v = __ldg(&vals[i]);
            const float* sp = support + (size_t)c * OUT;
            #pragma unroll
            for (int j = 0; j < J; j++)
                acc[j] = fmaf(v, __ldg(&sp[lane + 32 * j]), acc[j]);
        }
        float* trow = t + (size_t)row * OUT;
        #pragma unroll
        for (int j = 0; j < J; j++) {
            float a = acc[j];
            // leaky_relu(0.2) then elu: sign preserved -> single branch
            float tv = (a > 0.f) ? a : expm1f(0.2f * a);
            trow[lane + 32 * j] = tv;
            atomicAdd(&ssum[lane + 32 * j], tv);
            atomicAdd(&ssq[lane + 32 * j], tv * tv);
        }
    }
    __syncthreads();
    for (int i = tid; i < OUT; i += blockDim.x) {
        atomicAdd(&g_sum[LAYER][i], ssum[i]);
        atomicAdd(&g_sq[LAYER][i], ssq[i]);
    }
}

// ---------------------------------------------------------------------------
// BatchNorm (affine=False, biased var): out = (t - mean) * rsqrt(var + eps)
template<int OUT, int LAYER>
__global__ void norm_kernel(const float* __restrict__ t, float* __restrict__ out, int N) {
    const float invN = 1.f / (float)N;
    size_t total = (size_t)N * OUT;
    for (size_t i = (size_t)blockIdx.x * blockDim.x + threadIdx.x; i < total;
         i += (size_t)gridDim.x * blockDim.x) {
        int c = (int)(i & (OUT - 1));
        float mean = g_sum[LAYER][c] * invN;
        float var  = g_sq[LAYER][c] * invN - mean * mean;
        float r = rsqrtf(var + 1e-5f);
        out[i] = (t[i] - mean) * r;
    }
}

// ---------------------------------------------------------------------------
extern "C" void kernel_launch(void* const* d_in, const int* in_sizes, int n_in,
                              void* d_out, int out_size) {
    const float* x        = (const float*)d_in[0];
    const int*   adj_row  = (const int*)d_in[1];
    const int*   adj_col  = (const int*)d_in[2];
    const float* adj_vals = (const float*)d_in[3];
    const float* W1 = (const float*)d_in[4];
    const float* W2 = (const float*)d_in[5];
    const float* W3 = (const float*)d_in[6];
    const float* W4 = (const float*)d_in[7];
    float* out = (float*)d_out;

    const int N = in_sizes[0] / 256;
    const int E = in_sizes[1];

    float* g_support_p; cudaGetSymbolAddress((void**)&g_support_p, g_support);
    float* g_t_p;       cudaGetSymbolAddress((void**)&g_t_p, g_t);

    float* h1 = out;                       // [N,128]
    float* h2 = out + (size_t)N * 128;     // [N,128]
    float* h3 = out + (size_t)N * 256;     // [N,64]
    float* h4 = out + (size_t)N * 320;     // [N,32]

    zero_stats_kernel<<<1, 128>>>();
    rowptr_kernel<<<(N + 256) / 256, 256>>>(adj_row, N, E);

    dim3 gthr(16, 16);
    const int gemm_blocks = (N + 63) / 64;
    const int spmm_blocks = (N + 7) / 8;
    const int norm_blocks = 1184;  // 8 * 148

    // Layer 1: x[N,256] @ W1[256,128]
    gemm_kernel<256, 128><<<gemm_blocks, gthr>>>(x, W1, g_support_p, N);
    spmm_kernel<128, 0><<<spmm_blocks, 256>>>(g_support_p, adj_col, adj_vals, g_t_p, N);
    norm_kernel<128, 0><<<norm_blocks, 256>>>(g_t_p, h1, N);

    // Layer 2: h1[N,128] @ W2[128,128]
    gemm_kernel<128, 128><<<gemm_blocks, gthr>>>(h1, W2, g_support_p, N);
    spmm_kernel<128, 1><<<spmm_blocks, 256>>>(g_support_p, adj_col, adj_vals, g_t_p, N);
    norm_kernel<128, 1><<<norm_blocks, 256>>>(g_t_p, h2, N);

    // Layer 3: h2[N,128] @ W3[128,64]
    gemm_kernel<128, 64><<<gemm_blocks, gthr>>>(h2, W3, g_support_p, N);
    spmm_kernel<64, 2><<<spmm_blocks, 256>>>(g_support_p, adj_col, adj_vals, g_t_p, N);
    norm_kernel<64, 2><<<norm_blocks, 256>>>(g_t_p, h3, N);

    // Layer 4: h3[N,64] @ W4[64,32]
    gemm_kernel<64, 32><<<gemm_blocks, gthr>>>(h3, W4, g_support_p, N);
    spmm_kernel<32, 3><<<spmm_blocks, 256>>>(g_support_p, adj_col, adj_vals, g_t_p, N);
    norm_kernel<32, 3><<<norm_blocks, 256>>>(g_t_p, h4, N);
}

// round 3
// speedup vs baseline: 1.0004x; 1.0004x over previous
#include <cuda_runtime.h>
#include <cuda_bf16.h>
#include <math.h>

#define NMAX 100000
#define EMAX 1600000

// Scratch (allocation-free rule: __device__ globals)
__device__ float g_support[(size_t)NMAX * 128];
__device__ float g_t[(size_t)NMAX * 128];
__device__ float g_sum[4][128];
__device__ float g_sq[4][128];
__device__ int   g_rowptr[NMAX + 1];

// ---------------------------------------------------------------------------
// Zero the BN stat accumulators (all 4 layers) once per launch.
__global__ void zero_stats_kernel() {
    int i = threadIdx.x;
    if (i < 128) {
        #pragma unroll
        for (int l = 0; l < 4; l++) { g_sum[l][i] = 0.f; g_sq[l][i] = 0.f; }
    }
}

// ---------------------------------------------------------------------------
// CSR row_ptr from sorted adj_row via binary search (lower_bound of r).
__global__ void rowptr_kernel(const int* __restrict__ adj_row, int N, int E) {
    int r = blockIdx.x * blockDim.x + threadIdx.x;
    if (r > N) return;
    int lo = 0, hi = E;
    while (lo < hi) {
        int mid = (lo + hi) >> 1;
        if (adj_row[mid] < r) lo = mid + 1; else hi = mid;
    }
    g_rowptr[r] = lo;
}

// ---------------------------------------------------------------------------
// Tiled fp32 SGEMM: C[N,OUT] = A[N,K] @ W[K,OUT]
// BM=64 rows/block, BK=32, 16x16 threads, each thread: 4 x (OUT/16) outputs.
template<int K, int OUT>
__global__ void gemm_kernel(const float* __restrict__ A, const float* __restrict__ W,
                            float* __restrict__ C, int N) {
    constexpr int BM = 64, BK = 32;
    constexpr int TM = 4;
    constexpr int TN = OUT / 16;           // 8, 8, 4, 2
    __shared__ float As[BK][BM];           // A tile, transposed
    __shared__ float Ws[BK][OUT];

    const int tx = threadIdx.x;            // 0..15 -> col groups
    const int ty = threadIdx.y;            // 0..15 -> row groups
    const int tid = ty * 16 + tx;
    const int row0 = blockIdx.x * BM;

    float acc[TM][TN];
    #pragma unroll
    for (int i = 0; i < TM; i++)
        #pragma unroll
        for (int j = 0; j < TN; j++) acc[i][j] = 0.f;

    for (int kb = 0; kb < K; kb += BK) {
        // Load A tile (transposed): 64x32 elems, coalesced over k
        #pragma unroll
        for (int p = 0; p < (BM * BK) / 256; p++) {
            int idx = p * 256 + tid;
            int r = idx / BK, k = idx % BK;
            int gr = row0 + r;
            float v = (gr < N) ? A[(size_t)gr * K + kb + k] : 0.f;
            As[k][r] = v;
        }
        // Load W tile: BKxOUT elems, coalesced over c
        #pragma unroll
        for (int p = 0; p < (BK * OUT) / 256; p++) {
            int idx = p * 256 + tid;
            int k = idx / OUT, c = idx % OUT;
            Ws[k][c] = W[(size_t)(kb + k) * OUT + c];
        }
        __syncthreads();

        #pragma unroll
        for (int k = 0; k < BK; k++) {
            float a[TM], w[TN];
            #pragma unroll
            for (int i = 0; i < TM; i++) a[i] = As[k][ty * TM + i];
            #pragma unroll
            for (int j = 0; j < TN; j++) w[j] = Ws[k][tx * TN + j];
            #pragma unroll
            for (int i = 0; i < TM; i++)
                #pragma unroll
                for (int j = 0; j < TN; j++)
                    acc[i][j] = fmaf(a[i], w[j], acc[i][j]);
        }
        __syncthreads();
    }

    #pragma unroll
    for (int i = 0; i < TM; i++) {
        int gr = row0 + ty * TM + i;
        if (gr < N) {
            float* crow = C + (size_t)gr * OUT + tx * TN;
            #pragma unroll
            for (int j = 0; j < TN; j++) crow[j] = acc[i][j];
        }
    }
}

// ---------------------------------------------------------------------------
// SpMM (warp per row, sorted rows / CSR ranges) + leaky_relu + elu fused,
// plus block-local BN stat accumulation (sum, sumsq per column).
template<int OUT, int LAYER>
__global__ void spmm_kernel(const float* __restrict__ support,
                            const int* __restrict__ col,
                            const float* __restrict__ vals,
                            float* __restrict__ t, int N) {
    constexpr int J = OUT / 32;
    __shared__ float ssum[OUT], ssq[OUT];
    const int tid = threadIdx.x;
    for (int i = tid; i < OUT; i += blockDim.x) { ssum[i] = 0.f; ssq[i] = 0.f; }
    __syncthreads();

    const int lane = tid & 31;
    const int warp = tid >> 5;
    const int row = blockIdx.x * 8 + warp;

    if (row < N) {
        float acc[J];
        #pragma unroll
        for (int j = 0; j < J; j++) acc[j] = 0.f;

        const int s = g_rowptr[row];
        const int e = g_rowptr[row + 1];
        for (int i = s; i < e; i++) {
            int c = __ldg(&col[i]);
            float v = __ldg(&vals[i]);
            const float* sp = support + (size_t)c * OUT;
            #pragma unroll
            for (int j = 0; j < J; j++)
                acc[j] = fmaf(v, __ldg(&sp[lane + 32 * j]), acc[j]);
        }
        float* trow = t + (size_t)row * OUT;
        #pragma unroll
        for (int j = 0; j < J; j++) {
            float a = acc[j];
            // leaky_relu(0.2) then elu: sign preserved -> single branch
            float tv = (a > 0.f) ? a : expm1f(0.2f * a);
            trow[lane + 32 * j] = tv;
            atomicAdd(&ssum[lane + 32 * j], tv);
            atomicAdd(&ssq[lane + 32 * j], tv * tv);
        }
    }
    __syncthreads();
    for (int i = tid; i < OUT; i += blockDim.x) {
        atomicAdd(&g_sum[LAYER][i], ssum[i]);
        atomicAdd(&g_sq[LAYER][i], ssq[i]);
    }
}

// ---------------------------------------------------------------------------
// BatchNorm (affine=False, biased var): out = (t - mean) * rsqrt(var + eps)
template<int OUT, int LAYER>
__global__ void norm_kernel(const float* __restrict__ t, float* __restrict__ out, int N) {
    const float invN = 1.f / (float)N;
    size_t total = (size_t)N * OUT;
    for (size_t i = (size_t)blockIdx.x * blockDim.x + threadIdx.x; i < total;
         i += (size_t)gridDim.x * blockDim.x) {
        int c = (int)(i & (OUT - 1));
        float mean = g_sum[LAYER][c] * invN;
        float var  = g_sq[LAYER][c] * invN - mean * mean;
        float r = rsqrtf(var + 1e-5f);
        out[i] = (t[i] - mean) * r;
    }
}

// ---------------------------------------------------------------------------
extern "C" void kernel_launch(void* const* d_in, const int* in_sizes, int n_in,
                              void* d_out, int out_size) {
    const float* x        = (const float*)d_in[0];
    const int*   adj_row  = (const int*)d_in[1];
    const int*   adj_col  = (const int*)d_in[2];
    const float* adj_vals = (const float*)d_in[3];
    const float* W1 = (const float*)d_in[4];
    const float* W2 = (const float*)d_in[5];
    const float* W3 = (const float*)d_in[6];
    const float* W4 = (const float*)d_in[7];
    float* out = (float*)d_out;

    const int N = in_sizes[0] / 256;
    const int E = in_sizes[1];

    float* g_support_p; cudaGetSymbolAddress((void**)&g_support_p, g_support);
    float* g_t_p;       cudaGetSymbolAddress((void**)&g_t_p, g_t);

    float* h1 = out;                       // [N,128]
    float* h2 = out + (size_t)N * 128;     // [N,128]
    float* h3 = out + (size_t)N * 256;     // [N,64]
    float* h4 = out + (size_t)N * 320;     // [N,32]

    zero_stats_kernel<<<1, 128>>>();
    rowptr_kernel<<<(N + 256) / 256, 256>>>(adj_row, N, E);

    dim3 gthr(16, 16);
    const int gemm_blocks = (N + 63) / 64;
    const int spmm_blocks = (N + 7) / 8;
    const int norm_blocks = 1184;  // 8 * 148

    // Layer 1: x[N,256] @ W1[256,128]
    gemm_kernel<256, 128><<<gemm_blocks, gthr>>>(x, W1, g_support_p, N);
    spmm_kernel<128, 0><<<spmm_blocks, 256>>>(g_support_p, adj_col, adj_vals, g_t_p, N);
    norm_kernel<128, 0><<<norm_blocks, 256>>>(g_t_p, h1, N);

    // Layer 2: h1[N,128] @ W2[128,128]
    gemm_kernel<128, 128><<<gemm_blocks, gthr>>>(h1, W2, g_support_p, N);
    spmm_kernel<128, 1><<<spmm_blocks, 256>>>(g_support_p, adj_col, adj_vals, g_t_p, N);
    norm_kernel<128, 1><<<norm_blocks, 256>>>(g_t_p, h2, N);

    // Layer 3: h2[N,128] @ W3[128,64]
    gemm_kernel<128, 64><<<gemm_blocks, gthr>>>(h2, W3, g_support_p, N);
    spmm_kernel<64, 2><<<spmm_blocks, 256>>>(g_support_p, adj_col, adj_vals, g_t_p, N);
    norm_kernel<64, 2><<<norm_blocks, 256>>>(g_t_p, h3, N);

    // Layer 4: h3[N,64] @ W4[64,32]
    gemm_kernel<64, 32><<<gemm_blocks, gthr>>>(h3, W4, g_support_p, N);
    spmm_kernel<32, 3><<<spmm_blocks, 256>>>(g_support_p, adj_col, adj_vals, g_t_p, N);
    norm_kernel<32, 3><<<norm_blocks, 256>>>(g_t_p, h4, N);
}

// round 4
// speedup vs baseline: 1.0008x; 1.0004x over previous
#include <cuda_runtime.h>
#include <cuda_bf16.h>
#include <math.h>

#define NMAX 100000
#define EMAX 1600000

// Scratch (allocation-free rule: __device__ globals)
__device__ float g_support[(size_t)NMAX * 128];
__device__ float g_t[(size_t)NMAX * 128];
__device__ float g_sum[4][128];
__device__ float g_sq[4][128];
__device__ int   g_rowptr[NMAX + 1];

// ---------------------------------------------------------------------------
// Zero the BN stat accumulators (all 4 layers) once per launch.
__global__ void zero_stats_kernel() {
    int i = threadIdx.x;
    if (i < 128) {
        #pragma unroll
        for (int l = 0; l < 4; l++) { g_sum[l][i] = 0.f; g_sq[l][i] = 0.f; }
    }
}

// ---------------------------------------------------------------------------
// CSR row_ptr from sorted adj_row via binary search (lower_bound of r).
__global__ void rowptr_kernel(const int* __restrict__ adj_row, int N, int E) {
    int r = blockIdx.x * blockDim.x + threadIdx.x;
    if (r > N) return;
    int lo = 0, hi = E;
    while (lo < hi) {
        int mid = (lo + hi) >> 1;
        if (adj_row[mid] < r) lo = mid + 1; else hi = mid;
    }
    g_rowptr[r] = lo;
}

// ---------------------------------------------------------------------------
// Tiled fp32 SGEMM: C[N,OUT] = A[N,K] @ W[K,OUT]
// BM=64 rows/block, BK=32, 16x16 threads, each thread: 4 x (OUT/16) outputs.
template<int K, int OUT>
__global__ void gemm_kernel(const float* __restrict__ A, const float* __restrict__ W,
                            float* __restrict__ C, int N) {
    constexpr int BM = 64, BK = 32;
    constexpr int TM = 4;
    constexpr int TN = OUT / 16;           // 8, 8, 4, 2
    __shared__ float As[BK][BM];           // A tile, transposed
    __shared__ float Ws[BK][OUT];

    const int tx = threadIdx.x;            // 0..15 -> col groups
    const int ty = threadIdx.y;            // 0..15 -> row groups
    const int tid = ty * 16 + tx;
    const int row0 = blockIdx.x * BM;

    float acc[TM][TN];
    #pragma unroll
    for (int i = 0; i < TM; i++)
        #pragma unroll
        for (int j = 0; j < TN; j++) acc[i][j] = 0.f;

    for (int kb = 0; kb < K; kb += BK) {
        // Load A tile (transposed): 64x32 elems, coalesced over k
        #pragma unroll
        for (int p = 0; p < (BM * BK) / 256; p++) {
            int idx = p * 256 + tid;
            int r = idx / BK, k = idx % BK;
            int gr = row0 + r;
            float v = (gr < N) ? A[(size_t)gr * K + kb + k] : 0.f;
            As[k][r] = v;
        }
        // Load W tile: BKxOUT elems, coalesced over c
        #pragma unroll
        for (int p = 0; p < (BK * OUT) / 256; p++) {
            int idx = p * 256 + tid;
            int k = idx / OUT, c = idx % OUT;
            Ws[k][c] = W[(size_t)(kb + k) * OUT + c];
        }
        __syncthreads();

        #pragma unroll
        for (int k = 0; k < BK; k++) {
            float a[TM], w[TN];
            #pragma unroll
            for (int i = 0; i < TM; i++) a[i] = As[k][ty * TM + i];
            #pragma unroll
            for (int j = 0; j < TN; j++) w[j] = Ws[k][tx * TN + j];
            #pragma unroll
            for (int i = 0; i < TM; i++)
                #pragma unroll
                for (int j = 0; j < TN; j++)
                    acc[i][j] = fmaf(a[i], w[j], acc[i][j]);
        }
        __syncthreads();
    }

    #pragma unroll
    for (int i = 0; i < TM; i++) {
        int gr = row0 + ty * TM + i;
        if (gr < N) {
            float* crow = C + (size_t)gr * OUT + tx * TN;
            #pragma unroll
            for (int j = 0; j < TN; j++) crow[j] = acc[i][j];
        }
    }
}

// ---------------------------------------------------------------------------
// SpMM (warp per row, sorted rows / CSR ranges) + leaky_relu + elu fused,
// plus block-local BN stat accumulation (sum, sumsq per column).
template<int OUT, int LAYER>
__global__ void spmm_kernel(const float* __restrict__ support,
                            const int* __restrict__ col,
                            const float* __restrict__ vals,
                            float* __restrict__ t, int N) {
    constexpr int J = OUT / 32;
    __shared__ float ssum[OUT], ssq[OUT];
    const int tid = threadIdx.x;
    for (int i = tid; i < OUT; i += blockDim.x) { ssum[i] = 0.f; ssq[i] = 0.f; }
    __syncthreads();

    const int lane = tid & 31;
    const int warp = tid >> 5;
    const int row = blockIdx.x * 8 + warp;

    if (row < N) {
        float acc[J];
        #pragma unroll
        for (int j = 0; j < J; j++) acc[j] = 0.f;

        const int s = g_rowptr[row];
        const int e = g_rowptr[row + 1];
        for (int i = s; i < e; i++) {
            int c = __ldg(&col[i]);
            float v = __ldg(&vals[i]);
            const float* sp = support + (size_t)c * OUT;
            #pragma unroll
            for (int j = 0; j < J; j++)
                acc[j] = fmaf(v, __ldg(&sp[lane + 32 * j]), acc[j]);
        }
        float* trow = t + (size_t)row * OUT;
        #pragma unroll
        for (int j = 0; j < J; j++) {
            float a = acc[j];
            // leaky_relu(0.2) then elu: sign preserved -> single branch
            float tv = (a > 0.f) ? a : expm1f(0.2f * a);
            trow[lane + 32 * j] = tv;
            atomicAdd(&ssum[lane + 32 * j], tv);
            atomicAdd(&ssq[lane + 32 * j], tv * tv);
        }
    }
    __syncthreads();
    for (int i = tid; i < OUT; i += blockDim.x) {
        atomicAdd(&g_sum[LAYER][i], ssum[i]);
        atomicAdd(&g_sq[LAYER][i], ssq[i]);
    }
}

// ---------------------------------------------------------------------------
// BatchNorm (affine=False, biased var): out = (t - mean) * rsqrt(var + eps)
template<int OUT, int LAYER>
__global__ void norm_kernel(const float* __restrict__ t, float* __restrict__ out, int N) {
    const float invN = 1.f / (float)N;
    size_t total = (size_t)N * OUT;
    for (size_t i = (size_t)blockIdx.x * blockDim.x + threadIdx.x; i < total;
         i += (size_t)gridDim.x * blockDim.x) {
        int c = (int)(i & (OUT - 1));
        float mean = g_sum[LAYER][c] * invN;
        float var  = g_sq[LAYER][c] * invN - mean * mean;
        float r = rsqrtf(var + 1e-5f);
        out[i] = (t[i] - mean) * r;
    }
}

// ---------------------------------------------------------------------------
extern "C" void kernel_launch(void* const* d_in, const int* in_sizes, int n_in,
                              void* d_out, int out_size) {
    const float* x        = (const float*)d_in[0];
    const int*   adj_row  = (const int*)d_in[1];
    const int*   adj_col  = (const int*)d_in[2];
    const float* adj_vals = (const float*)d_in[3];
    const float* W1 = (const float*)d_in[4];
    const float* W2 = (const float*)d_in[5];
    const float* W3 = (const float*)d_in[6];
    const float* W4 = (const float*)d_in[7];
    float* out = (float*)d_out;

    const int N = in_sizes[0] / 256;
    const int E = in_sizes[1];

    float* g_support_p; cudaGetSymbolAddress((void**)&g_support_p, g_support);
    float* g_t_p;       cudaGetSymbolAddress((void**)&g_t_p, g_t);

    float* h1 = out;                       // [N,128]
    float* h2 = out + (size_t)N * 128;     // [N,128]
    float* h3 = out + (size_t)N * 256;     // [N,64]
    float* h4 = out + (size_t)N * 320;     // [N,32]

    zero_stats_kernel<<<1, 128>>>();
    rowptr_kernel<<<(N + 256) / 256, 256>>>(adj_row, N, E);

    dim3 gthr(16, 16);
    const int gemm_blocks = (N + 63) / 64;
    const int spmm_blocks = (N + 7) / 8;
    const int norm_blocks = 1184;  // 8 * 148

    // Layer 1: x[N,256] @ W1[256,128]
    gemm_kernel<256, 128><<<gemm_blocks, gthr>>>(x, W1, g_support_p, N);
    spmm_kernel<128, 0><<<spmm_blocks, 256>>>(g_support_p, adj_col, adj_vals, g_t_p, N);
    norm_kernel<128, 0><<<norm_blocks, 256>>>(g_t_p, h1, N);

    // Layer 2: h1[N,128] @ W2[128,128]
    gemm_kernel<128, 128><<<gemm_blocks, gthr>>>(h1, W2, g_support_p, N);
    spmm_kernel<128, 1><<<spmm_blocks, 256>>>(g_support_p, adj_col, adj_vals, g_t_p, N);
    norm_kernel<128, 1><<<norm_blocks, 256>>>(g_t_p, h2, N);

    // Layer 3: h2[N,128] @ W3[128,64]
    gemm_kernel<128, 64><<<gemm_blocks, gthr>>>(h2, W3, g_support_p, N);
    spmm_kernel<64, 2><<<spmm_blocks, 256>>>(g_support_p, adj_col, adj_vals, g_t_p, N);
    norm_kernel<64, 2><<<norm_blocks, 256>>>(g_t_p, h3, N);

    // Layer 4: h3[N,64] @ W4[64,32]
    gemm_kernel<64, 32><<<gemm_blocks, gthr>>>(h3, W4, g_support_p, N);
    spmm_kernel<32, 3><<<spmm_blocks, 256>>>(g_support_p, adj_col, adj_vals, g_t_p, N);
    norm_kernel<32, 3><<<norm_blocks, 256>>>(g_t_p, h4, N);
}

// round 5
// speedup vs baseline: 1.0011x; 1.0003x over previous
#include <cuda_runtime.h>
#include <cuda_bf16.h>
#include <math.h>

#define NMAX 100000
#define EMAX 1600000

// Scratch (allocation-free rule: __device__ globals)
__device__ float g_support[(size_t)NMAX * 128];
__device__ float g_t[(size_t)NMAX * 128];
__device__ float g_sum[4][128];
__device__ float g_sq[4][128];
__device__ int   g_rowptr[NMAX + 1];

// ---------------------------------------------------------------------------
// Zero the BN stat accumulators (all 4 layers) once per launch.
__global__ void zero_stats_kernel() {
    int i = threadIdx.x;
    if (i < 128) {
        #pragma unroll
        for (int l = 0; l < 4; l++) { g_sum[l][i] = 0.f; g_sq[l][i] = 0.f; }
    }
}

// ---------------------------------------------------------------------------
// CSR row_ptr from sorted adj_row via binary search (lower_bound of r).
__global__ void rowptr_kernel(const int* __restrict__ adj_row, int N, int E) {
    int r = blockIdx.x * blockDim.x + threadIdx.x;
    if (r > N) return;
    int lo = 0, hi = E;
    while (lo < hi) {
        int mid = (lo + hi) >> 1;
        if (adj_row[mid] < r) lo = mid + 1; else hi = mid;
    }
    g_rowptr[r] = lo;
}

// ---------------------------------------------------------------------------
// Tiled fp32 SGEMM: C[N,OUT] = A[N,K] @ W[K,OUT]
// BM=64 rows/block, BK=32, 16x16 threads, each thread: 4 x (OUT/16) outputs.
template<int K, int OUT>
__global__ void gemm_kernel(const float* __restrict__ A, const float* __restrict__ W,
                            float* __restrict__ C, int N) {
    constexpr int BM = 64, BK = 32;
    constexpr int TM = 4;
    constexpr int TN = OUT / 16;           // 8, 8, 4, 2
    __shared__ float As[BK][BM];           // A tile, transposed
    __shared__ float Ws[BK][OUT];

    const int tx = threadIdx.x;            // 0..15 -> col groups
    const int ty = threadIdx.y;            // 0..15 -> row groups
    const int tid = ty * 16 + tx;
    const int row0 = blockIdx.x * BM;

    float acc[TM][TN];
    #pragma unroll
    for (int i = 0; i < TM; i++)
        #pragma unroll
        for (int j = 0; j < TN; j++) acc[i][j] = 0.f;

    for (int kb = 0; kb < K; kb += BK) {
        // Load A tile (transposed): 64x32 elems, coalesced over k
        #pragma unroll
        for (int p = 0; p < (BM * BK) / 256; p++) {
            int idx = p * 256 + tid;
            int r = idx / BK, k = idx % BK;
            int gr = row0 + r;
            float v = (gr < N) ? A[(size_t)gr * K + kb + k] : 0.f;
            As[k][r] = v;
        }
        // Load W tile: BKxOUT elems, coalesced over c
        #pragma unroll
        for (int p = 0; p < (BK * OUT) / 256; p++) {
            int idx = p * 256 + tid;
            int k = idx / OUT, c = idx % OUT;
            Ws[k][c] = W[(size_t)(kb + k) * OUT + c];
        }
        __syncthreads();

        #pragma unroll
        for (int k = 0; k < BK; k++) {
            float a[TM], w[TN];
            #pragma unroll
            for (int i = 0; i < TM; i++) a[i] = As[k][ty * TM + i];
            #pragma unroll
            for (int j = 0; j < TN; j++) w[j] = Ws[k][tx * TN + j];
            #pragma unroll
            for (int i = 0; i < TM; i++)
                #pragma unroll
                for (int j = 0; j < TN; j++)
                    acc[i][j] = fmaf(a[i], w[j], acc[i][j]);
        }
        __syncthreads();
    }

    #pragma unroll
    for (int i = 0; i < TM; i++) {
        int gr = row0 + ty * TM + i;
        if (gr < N) {
            float* crow = C + (size_t)gr * OUT + tx * TN;
            #pragma unroll
            for (int j = 0; j < TN; j++) crow[j] = acc[i][j];
        }
    }
}

// ---------------------------------------------------------------------------
// SpMM (warp per row, sorted rows / CSR ranges) + leaky_relu + elu fused,
// plus block-local BN stat accumulation (sum, sumsq per column).
template<int OUT, int LAYER>
__global__ void spmm_kernel(const float* __restrict__ support,
                            const int* __restrict__ col,
                            const float* __restrict__ vals,
                            float* __restrict__ t, int N) {
    constexpr int J = OUT / 32;
    __shared__ float ssum[OUT], ssq[OUT];
    const int tid = threadIdx.x;
    for (int i = tid; i < OUT; i += blockDim.x) { ssum[i] = 0.f; ssq[i] = 0.f; }
    __syncthreads();

    const int lane = tid & 31;
    const int warp = tid >> 5;
    const int row = blockIdx.x * 8 + warp;

    if (row < N) {
        float acc[J];
        #pragma unroll
        for (int j = 0; j < J; j++) acc[j] = 0.f;

        const int s = g_rowptr[row];
        const int e = g_rowptr[row + 1];
        for (int i = s; i < e; i++) {
            int c = __ldg(&col[i]);
            float v = __ldg(&vals[i]);
            const float* sp = support + (size_t)c * OUT;
            #pragma unroll
            for (int j = 0; j < J; j++)
                acc[j] = fmaf(v, __ldg(&sp[lane + 32 * j]), acc[j]);
        }
        float* trow = t + (size_t)row * OUT;
        #pragma unroll
        for (int j = 0; j < J; j++) {
            float a = acc[j];
            // leaky_relu(0.2) then elu: sign preserved -> single branch
            float tv = (a > 0.f) ? a : expm1f(0.2f * a);
            trow[lane + 32 * j] = tv;
            atomicAdd(&ssum[lane + 32 * j], tv);
            atomicAdd(&ssq[lane + 32 * j], tv * tv);
        }
    }
    __syncthreads();
    for (int i = tid; i < OUT; i += blockDim.x) {
        atomicAdd(&g_sum[LAYER][i], ssum[i]);
        atomicAdd(&g_sq[LAYER][i], ssq[i]);
    }
}

// ---------------------------------------------------------------------------
// BatchNorm (affine=False, biased var): out = (t - mean) * rsqrt(var + eps)
template<int OUT, int LAYER>
__global__ void norm_kernel(const float* __restrict__ t, float* __restrict__ out, int N) {
    const float invN = 1.f / (float)N;
    size_t total = (size_t)N * OUT;
    for (size_t i = (size_t)blockIdx.x * blockDim.x + threadIdx.x; i < total;
         i += (size_t)gridDim.x * blockDim.x) {
        int c = (int)(i & (OUT - 1));
        float mean = g_sum[LAYER][c] * invN;
        float var  = g_sq[LAYER][c] * invN - mean * mean;
        float r = rsqrtf(var + 1e-5f);
        out[i] = (t[i] - mean) * r;
    }
}

// ---------------------------------------------------------------------------
extern "C" void kernel_launch(void* const* d_in, const int* in_sizes, int n_in,
                              void* d_out, int out_size) {
    const float* x        = (const float*)d_in[0];
    const int*   adj_row  = (const int*)d_in[1];
    const int*   adj_col  = (const int*)d_in[2];
    const float* adj_vals = (const float*)d_in[3];
    const float* W1 = (const float*)d_in[4];
    const float* W2 = (const float*)d_in[5];
    const float* W3 = (const float*)d_in[6];
    const float* W4 = (const float*)d_in[7];
    float* out = (float*)d_out;

    const int N = in_sizes[0] / 256;
    const int E = in_sizes[1];

    float* g_support_p; cudaGetSymbolAddress((void**)&g_support_p, g_support);
    float* g_t_p;       cudaGetSymbolAddress((void**)&g_t_p, g_t);

    float* h1 = out;                       // [N,128]
    float* h2 = out + (size_t)N * 128;     // [N,128]
    float* h3 = out + (size_t)N * 256;     // [N,64]
    float* h4 = out + (size_t)N * 320;     // [N,32]

    zero_stats_kernel<<<1, 128>>>();
    rowptr_kernel<<<(N + 256) / 256, 256>>>(adj_row, N, E);

    dim3 gthr(16, 16);
    const int gemm_blocks = (N + 63) / 64;
    const int spmm_blocks = (N + 7) / 8;
    const int norm_blocks = 1184;  // 8 * 148

    // Layer 1: x[N,256] @ W1[256,128]
    gemm_kernel<256, 128><<<gemm_blocks, gthr>>>(x, W1, g_support_p, N);
    spmm_kernel<128, 0><<<spmm_blocks, 256>>>(g_support_p, adj_col, adj_vals, g_t_p, N);
    norm_kernel<128, 0><<<norm_blocks, 256>>>(g_t_p, h1, N);

    // Layer 2: h1[N,128] @ W2[128,128]
    gemm_kernel<128, 128><<<gemm_blocks, gthr>>>(h1, W2, g_support_p, N);
    spmm_kernel<128, 1><<<spmm_blocks, 256>>>(g_support_p, adj_col, adj_vals, g_t_p, N);
    norm_kernel<128, 1><<<norm_blocks, 256>>>(g_t_p, h2, N);

    // Layer 3: h2[N,128] @ W3[128,64]
    gemm_kernel<128, 64><<<gemm_blocks, gthr>>>(h2, W3, g_support_p, N);
    spmm_kernel<64, 2><<<spmm_blocks, 256>>>(g_support_p, adj_col, adj_vals, g_t_p, N);
    norm_kernel<64, 2><<<norm_blocks, 256>>>(g_t_p, h3, N);

    // Layer 4: h3[N,64] @ W4[64,32]
    gemm_kernel<64, 32><<<gemm_blocks, gthr>>>(h3, W4, g_support_p, N);
    spmm_kernel<32, 3><<<spmm_blocks, 256>>>(g_support_p, adj_col, adj_vals, g_t_p, N);
    norm_kernel<32, 3><<<norm_blocks, 256>>>(g_t_p, h4, N);
}

// round 6
// speedup vs baseline: 1.5120x; 1.5104x over previous
#include <cuda_runtime.h>
#include <cuda_bf16.h>
#include <math.h>
#include <stdint.h>

#define NMAX 100000
#define EMAX 1600000

// Scratch (allocation-free rule: __device__ globals)
__device__ float g_support[(size_t)NMAX * 128];
__device__ float g_t[(size_t)NMAX * 128];
__device__ float g_sum[4][128];
__device__ float g_sq[4][128];
__device__ int   g_rowptr[NMAX + 1];

// ---------------------------------------------------------------------------
__global__ void zero_stats_kernel() {
    int i = threadIdx.x;
    if (i < 128) {
        #pragma unroll
        for (int l = 0; l < 4; l++) { g_sum[l][i] = 0.f; g_sq[l][i] = 0.f; }
    }
}

// ---------------------------------------------------------------------------
// CSR row_ptr from sorted adj_row via binary search (lower_bound of r).
__global__ void rowptr_kernel(const int* __restrict__ adj_row, int N, int E) {
    int r = blockIdx.x * blockDim.x + threadIdx.x;
    if (r > N) return;
    int lo = 0, hi = E;
    while (lo < hi) {
        int mid = (lo + hi) >> 1;
        if (adj_row[mid] < r) lo = mid + 1; else hi = mid;
    }
    g_rowptr[r] = lo;
}

// ---------------------------------------------------------------------------
// tf32 helpers
__device__ __forceinline__ uint32_t f2tf32(float v) {
    uint32_t r;
    asm("cvt.rna.tf32.f32 %0, %1;" : "=r"(r) : "f"(v));
    return r;
}
__device__ __forceinline__ void tf32_split(float v, float& h, float& l) {
    uint32_t hu = f2tf32(v);
    h = __uint_as_float(hu);
    l = __uint_as_float(f2tf32(v - h));
}
__device__ __forceinline__ void mma_tf32(float c[4], const uint32_t a[4],
                                         uint32_t b0, uint32_t b1) {
    asm volatile(
        "mma.sync.aligned.m16n8k8.row.col.f32.tf32.tf32.f32 "
        "{%0,%1,%2,%3}, {%4,%5,%6,%7}, {%8,%9}, {%0,%1,%2,%3};\n"
        : "+f"(c[0]), "+f"(c[1]), "+f"(c[2]), "+f"(c[3])
        : "r"(a[0]), "r"(a[1]), "r"(a[2]), "r"(a[3]), "r"(b0), "r"(b1));
}

// ---------------------------------------------------------------------------
// Tensor-core tf32 GEMM with 3xTF32 compensation: C[N,OUT] = A[N,K] @ W[K,OUT]
// BM=128 rows/block, BK=16, 256 threads (8 warps).
template<int K, int OUT>
__global__ __launch_bounds__(256)
void gemm_tc(const float* __restrict__ A, const float* __restrict__ W,
             float* __restrict__ C, int N) {
    constexpr int BM = 128, BK = 16;
    constexpr int AST = BK + 4;            // 20: stride%32=20 -> g*20+t bijective (conflict-free frag LDS)
    constexpr int WST = OUT + 8;           // stride%32=8  -> t*8+g bijective
    constexpr int WARPS_M = (OUT >= 64) ? 4 : 8;
    constexpr int WARPS_N = 8 / WARPS_M;
    constexpr int WM = BM / WARPS_M;       // 32 or 16
    constexpr int WN = OUT / WARPS_N;      // 64 / 32 / 32
    constexpr int MT = WM / 16;            // 2 or 1
    constexpr int NT = WN / 8;             // 8 / 4 / 4

    __shared__ float Ah[BM][AST], Al[BM][AST];
    __shared__ float Wh[BK][WST], Wl[BK][WST];

    const int tid = threadIdx.x;
    const int w = tid >> 5, lane = tid & 31;
    const int g = lane >> 2, t = lane & 3;
    const int wm = (WARPS_N == 2) ? (w >> 1) : w;
    const int wn = (WARPS_N == 2) ? (w & 1) : 0;
    const int row0 = blockIdx.x * BM;

    float acc[MT][NT][4];
    #pragma unroll
    for (int mt = 0; mt < MT; mt++)
        #pragma unroll
        for (int nt = 0; nt < NT; nt++)
            #pragma unroll
            for (int q = 0; q < 4; q++) acc[mt][nt][q] = 0.f;

    for (int kb = 0; kb < K; kb += BK) {
        // --- A tile [128 rows x 16 k], split hi/lo, float4 I/O ---
        #pragma unroll
        for (int idx = tid; idx < BM * BK / 4; idx += 256) {
            int r = idx >> 2;
            int kq = (idx & 3) * 4;
            int gr = row0 + r;
            float4 v = make_float4(0.f, 0.f, 0.f, 0.f);
            if (gr < N) v = *(const float4*)(A + (size_t)gr * K + kb + kq);
            float4 h, l;
            tf32_split(v.x, h.x, l.x);
            tf32_split(v.y, h.y, l.y);
            tf32_split(v.z, h.z, l.z);
            tf32_split(v.w, h.w, l.w);
            *(float4*)&Ah[r][kq] = h;
            *(float4*)&Al[r][kq] = l;
        }
        // --- W tile [16 k x OUT], split hi/lo ---
        #pragma unroll
        for (int idx = tid; idx < BK * OUT / 4; idx += 256) {
            int k = idx / (OUT / 4);
            int nq = (idx % (OUT / 4)) * 4;
            float4 v = *(const float4*)(W + (size_t)(kb + k) * OUT + nq);
            float4 h, l;
            tf32_split(v.x, h.x, l.x);
            tf32_split(v.y, h.y, l.y);
            tf32_split(v.z, h.z, l.z);
            tf32_split(v.w, h.w, l.w);
            *(float4*)&Wh[k][nq] = h;
            *(float4*)&Wl[k][nq] = l;
        }
        __syncthreads();

        #pragma unroll
        for (int ks = 0; ks < BK; ks += 8) {
            uint32_t ah[MT][4], al[MT][4];
            #pragma unroll
            for (int mt = 0; mt < MT; mt++) {
                int m = wm * WM + mt * 16 + g;
                ah[mt][0] = __float_as_uint(Ah[m][ks + t]);
                ah[mt][1] = __float_as_uint(Ah[m + 8][ks + t]);
                ah[mt][2] = __float_as_uint(Ah[m][ks + t + 4]);
                ah[mt][3] = __float_as_uint(Ah[m + 8][ks + t + 4]);
                al[mt][0] = __float_as_uint(Al[m][ks + t]);
                al[mt][1] = __float_as_uint(Al[m + 8][ks + t]);
                al[mt][2] = __float_as_uint(Al[m][ks + t + 4]);
                al[mt][3] = __float_as_uint(Al[m + 8][ks + t + 4]);
            }
            #pragma unroll
            for (int nt = 0; nt < NT; nt++) {
                int n = wn * WN + nt * 8 + g;
                uint32_t bh0 = __float_as_uint(Wh[ks + t][n]);
                uint32_t bh1 = __float_as_uint(Wh[ks + t + 4][n]);
                uint32_t bl0 = __float_as_uint(Wl[ks + t][n]);
                uint32_t bl1 = __float_as_uint(Wl[ks + t + 4][n]);
                #pragma unroll
                for (int mt = 0; mt < MT; mt++) {
                    mma_tf32(acc[mt][nt], ah[mt], bh0, bh1);  // hi*hi
                    mma_tf32(acc[mt][nt], ah[mt], bl0, bl1);  // hi*lo
                    mma_tf32(acc[mt][nt], al[mt], bh0, bh1);  // lo*hi
                }
            }
        }
        __syncthreads();
    }

    // Epilogue: c0,c1 at (row, t*2), c2,c3 at (row+8, t*2)
    #pragma unroll
    for (int mt = 0; mt < MT; mt++) {
        int r0 = row0 + wm * WM + mt * 16 + g;
        #pragma unroll
        for (int nt = 0; nt < NT; nt++) {
            int n = wn * WN + nt * 8 + t * 2;
            if (r0 < N)
                *(float2*)(C + (size_t)r0 * OUT + n) =
                    make_float2(acc[mt][nt][0], acc[mt][nt][1]);
            if (r0 + 8 < N)
                *(float2*)(C + (size_t)(r0 + 8) * OUT + n) =
                    make_float2(acc[mt][nt][2], acc[mt][nt][3]);
        }
    }
}

// ---------------------------------------------------------------------------
// SpMM (warp per row, CSR) + leaky_relu + elu fused, vectorized gathers,
// 2-edge unroll, block-local BN stat accumulation.
template<int OUT, int LAYER>
__global__ void spmm_kernel(const float* __restrict__ support,
                            const int* __restrict__ col,
                            const float* __restrict__ vals,
                            float* __restrict__ t, int N) {
    constexpr int VEC = OUT / 32;          // 4 / 2 / 1
    __shared__ float ssum[OUT], ssq[OUT];
    const int tid = threadIdx.x;
    for (int i = tid; i < OUT; i += blockDim.x) { ssum[i] = 0.f; ssq[i] = 0.f; }
    __syncthreads();

    const int lane = tid & 31;
    const int warp = tid >> 5;
    const int row = blockIdx.x * 8 + warp;

    if (row < N) {
        float acc[VEC];
        #pragma unroll
        for (int j = 0; j < VEC; j++) acc[j] = 0.f;

        const int s = g_rowptr[row];
        const int e = g_rowptr[row + 1];
        const int base = lane * VEC;

        int i = s;
        for (; i + 2 <= e; i += 2) {
            int c0 = __ldg(&col[i]);
            int c1 = __ldg(&col[i + 1]);
            float v0 = __ldg(&vals[i]);
            float v1 = __ldg(&vals[i + 1]);
            const float* p0 = support + (size_t)c0 * OUT + base;
            const float* p1 = support + (size_t)c1 * OUT + base;
            if constexpr (VEC == 4) {
                float4 m0 = *(const float4*)p0;
                float4 m1 = *(const float4*)p1;
                acc[0] = fmaf(v1, m1.x, fmaf(v0, m0.x, acc[0]));
                acc[1] = fmaf(v1, m1.y, fmaf(v0, m0.y, acc[1]));
                acc[2] = fmaf(v1, m1.z, fmaf(v0, m0.z, acc[2]));
                acc[3] = fmaf(v1, m1.w, fmaf(v0, m0.w, acc[3]));
            } else if constexpr (VEC == 2) {
                float2 m0 = *(const float2*)p0;
                float2 m1 = *(const float2*)p1;
                acc[0] = fmaf(v1, m1.x, fmaf(v0, m0.x, acc[0]));
                acc[1] = fmaf(v1, m1.y, fmaf(v0, m0.y, acc[1]));
            } else {
                acc[0] = fmaf(v1, __ldg(p1), fmaf(v0, __ldg(p0), acc[0]));
            }
        }
        if (i < e) {
            int c0 = __ldg(&col[i]);
            float v0 = __ldg(&vals[i]);
            const float* p0 = support + (size_t)c0 * OUT + base;
            if constexpr (VEC == 4) {
                float4 m0 = *(const float4*)p0;
                acc[0] = fmaf(v0, m0.x, acc[0]);
                acc[1] = fmaf(v0, m0.y, acc[1]);
                acc[2] = fmaf(v0, m0.z, acc[2]);
                acc[3] = fmaf(v0, m0.w, acc[3]);
            } else if constexpr (VEC == 2) {
                float2 m0 = *(const float2*)p0;
                acc[0] = fmaf(v0, m0.x, acc[0]);
                acc[1] = fmaf(v0, m0.y, acc[1]);
            } else {
                acc[0] = fmaf(v0, __ldg(p0), acc[0]);
            }
        }

        // leaky_relu(0.2) then elu; sign preserved -> single branch
        float tv[VEC];
        #pragma unroll
        for (int j = 0; j < VEC; j++) {
            float a = acc[j];
            tv[j] = (a > 0.f) ? a : expm1f(0.2f * a);
        }
        float* trow = t + (size_t)row * OUT + base;
        if constexpr (VEC == 4)
            *(float4*)trow = make_float4(tv[0], tv[1], tv[2], tv[3]);
        else if constexpr (VEC == 2)
            *(float2*)trow = make_float2(tv[0], tv[1]);
        else
            trow[0] = tv[0];
        #pragma unroll
        for (int j = 0; j < VEC; j++) {
            atomicAdd(&ssum[base + j], tv[j]);
            atomicAdd(&ssq[base + j], tv[j] * tv[j]);
        }
    }
    __syncthreads();
    for (int i = tid; i < OUT; i += blockDim.x) {
        atomicAdd(&g_sum[LAYER][i], ssum[i]);
        atomicAdd(&g_sq[LAYER][i], ssq[i]);
    }
}

// ---------------------------------------------------------------------------
// BatchNorm (affine=False, biased var): out = (t - mean) * rsqrt(var + eps)
template<int OUT, int LAYER>
__global__ void norm_kernel(const float* __restrict__ t, float* __restrict__ out, int N) {
    __shared__ float mean_s[OUT], r_s[OUT];
    const float invN = 1.f / (float)N;
    for (int i = threadIdx.x; i < OUT; i += blockDim.x) {
        float m = g_sum[LAYER][i] * invN;
        float var = g_sq[LAYER][i] * invN - m * m;
        mean_s[i] = m;
        r_s[i] = rsqrtf(var + 1e-5f);
    }
    __syncthreads();
    const float4* t4 = (const float4*)t;
    float4* o4 = (float4*)out;
    size_t total4 = (size_t)N * OUT / 4;
    for (size_t i = (size_t)blockIdx.x * blockDim.x + threadIdx.x; i < total4;
         i += (size_t)gridDim.x * blockDim.x) {
        int cb = (int)(i & (OUT / 4 - 1)) * 4;
        float4 v = t4[i];
        float4 r;
        r.x = (v.x - mean_s[cb + 0]) * r_s[cb + 0];
        r.y = (v.y - mean_s[cb + 1]) * r_s[cb + 1];
        r.z = (v.z - mean_s[cb + 2]) * r_s[cb + 2];
        r.w = (v.w - mean_s[cb + 3]) * r_s[cb + 3];
        o4[i] = r;
    }
}

// ---------------------------------------------------------------------------
extern "C" void kernel_launch(void* const* d_in, const int* in_sizes, int n_in,
                              void* d_out, int out_size) {
    const float* x        = (const float*)d_in[0];
    const int*   adj_row  = (const int*)d_in[1];
    const int*   adj_col  = (const int*)d_in[2];
    const float* adj_vals = (const float*)d_in[3];
    const float* W1 = (const float*)d_in[4];
    const float* W2 = (const float*)d_in[5];
    const float* W3 = (const float*)d_in[6];
    const float* W4 = (const float*)d_in[7];
    float* out = (float*)d_out;

    const int N = in_sizes[0] / 256;
    const int E = in_sizes[1];

    float* g_support_p; cudaGetSymbolAddress((void**)&g_support_p, g_support);
    float* g_t_p;       cudaGetSymbolAddress((void**)&g_t_p, g_t);

    float* h1 = out;                       // [N,128]
    float* h2 = out + (size_t)N * 128;     // [N,128]
    float* h3 = out + (size_t)N * 256;     // [N,64]
    float* h4 = out + (size_t)N * 320;     // [N,32]

    zero_stats_kernel<<<1, 128>>>();
    rowptr_kernel<<<(N + 256) / 256, 256>>>(adj_row, N, E);

    const int gemm_blocks = (N + 127) / 128;
    const int spmm_blocks = (N + 7) / 8;
    const int norm_blocks = 1184;  // 8 * 148

    // Layer 1: x[N,256] @ W1[256,128]
    gemm_tc<256, 128><<<gemm_blocks, 256>>>(x, W1, g_support_p, N);
    spmm_kernel<128, 0><<<spmm_blocks, 256>>>(g_support_p, adj_col, adj_vals, g_t_p, N);
    norm_kernel<128, 0><<<norm_blocks, 256>>>(g_t_p, h1, N);

    // Layer 2: h1[N,128] @ W2[128,128]
    gemm_tc<128, 128><<<gemm_blocks, 256>>>(h1, W2, g_support_p, N);
    spmm_kernel<128, 1><<<spmm_blocks, 256>>>(g_support_p, adj_col, adj_vals, g_t_p, N);
    norm_kernel<128, 1><<<norm_blocks, 256>>>(g_t_p, h2, N);

    // Layer 3: h2[N,128] @ W3[128,64]
    gemm_tc<128, 64><<<gemm_blocks, 256>>>(h2, W3, g_support_p, N);
    spmm_kernel<64, 2><<<spmm_blocks, 256>>>(g_support_p, adj_col, adj_vals, g_t_p, N);
    norm_kernel<64, 2><<<norm_blocks, 256>>>(g_t_p, h3, N);

    // Layer 4: h3[N,64] @ W4[64,32]
    gemm_tc<64, 32><<<gemm_blocks, 256>>>(h3, W4, g_support_p, N);
    spmm_kernel<32, 3><<<spmm_blocks, 256>>>(g_support_p, adj_col, adj_vals, g_t_p, N);
    norm_kernel<32, 3><<<norm_blocks, 256>>>(g_t_p, h4, N);
}

// round 7
// speedup vs baseline: 1.7148x; 1.1341x over previous
#include <cuda_runtime.h>
#include <cuda_bf16.h>
#include <math.h>
#include <stdint.h>

#define NMAX 100000
#define EMAX 1600000

// Scratch (allocation-free rule: __device__ globals)
__device__ float g_support[(size_t)NMAX * 128];
__device__ float g_t[(size_t)NMAX * 128];
__device__ float g_sum[4][128];
__device__ float g_sq[4][128];
__device__ int   g_rowptr[NMAX + 1];

// ---------------------------------------------------------------------------
__global__ void zero_stats_kernel() {
    int i = threadIdx.x;
    if (i < 128) {
        #pragma unroll
        for (int l = 0; l < 4; l++) { g_sum[l][i] = 0.f; g_sq[l][i] = 0.f; }
    }
}

// ---------------------------------------------------------------------------
// CSR row_ptr from sorted adj_row via binary search (lower_bound of r).
__global__ void rowptr_kernel(const int* __restrict__ adj_row, int N, int E) {
    int r = blockIdx.x * blockDim.x + threadIdx.x;
    if (r > N) return;
    int lo = 0, hi = E;
    while (lo < hi) {
        int mid = (lo + hi) >> 1;
        if (adj_row[mid] < r) lo = mid + 1; else hi = mid;
    }
    g_rowptr[r] = lo;
}

// ---------------------------------------------------------------------------
// tf32 helpers
__device__ __forceinline__ uint32_t f2tf32(float v) {
    uint32_t r;
    asm("cvt.rna.tf32.f32 %0, %1;" : "=r"(r) : "f"(v));
    return r;
}
__device__ __forceinline__ void tf32_split(float v, float& h, float& l) {
    uint32_t hu = f2tf32(v);
    h = __uint_as_float(hu);
    l = __uint_as_float(f2tf32(v - h));
}
__device__ __forceinline__ void mma_tf32(float c[4], const uint32_t a[4],
                                         uint32_t b0, uint32_t b1) {
    asm volatile(
        "mma.sync.aligned.m16n8k8.row.col.f32.tf32.tf32.f32 "
        "{%0,%1,%2,%3}, {%4,%5,%6,%7}, {%8,%9}, {%0,%1,%2,%3};\n"
        : "+f"(c[0]), "+f"(c[1]), "+f"(c[2]), "+f"(c[3])
        : "r"(a[0]), "r"(a[1]), "r"(a[2]), "r"(a[3]), "r"(b0), "r"(b1));
}

// ---------------------------------------------------------------------------
// Tensor-core tf32 GEMM with 3xTF32 compensation, fused input-BatchNorm:
//   If LAYER >= 0: A-input is pre-norm t of layer LAYER; each element is
//   normalized with that layer's global stats on load, the normalized value
//   is written to Hout (the layer's d_out slice), and fed to the mma.
// C[N,OUT] = norm(A)[N,K] @ W[K,OUT]. BM=128, BK=16, 256 threads (8 warps).
// Register-prefetch double buffering over the K loop.
template<int K, int OUT, int LAYER>
__global__ __launch_bounds__(256)
void gemm_tc(const float* __restrict__ A, const float* __restrict__ W,
             float* __restrict__ C, float* __restrict__ Hout, int N) {
    constexpr int BM = 128, BK = 16;
    constexpr int AST = BK + 4;            // 20: g*20+t bijective mod 32 (conflict-free)
    constexpr int WST = OUT + 8;           // stride%32=8 -> t*8+g bijective
    constexpr int WARPS_M = (OUT >= 64) ? 4 : 8;
    constexpr int WARPS_N = 8 / WARPS_M;
    constexpr int WM = BM / WARPS_M;       // 32 or 16
    constexpr int WN = OUT / WARPS_N;      // 64 / 32 / 32
    constexpr int MT = WM / 16;            // 2 or 1
    constexpr int NT = WN / 8;             // 8 / 4 / 4
    constexpr int NA = (BM * BK) / (4 * 256);    // float4 A loads per thread = 2
    constexpr int NW = (BK * OUT) / (4 * 256);   // float4 W loads per thread (0 => partial)
    constexpr int NWL = (NW > 0) ? NW : 1;

    __shared__ float Ah[BM][AST], Al[BM][AST];
    __shared__ float Wh[BK][WST], Wl[BK][WST];
    __shared__ float mean_s[128], r_s[128];

    const int tid = threadIdx.x;
    const int w = tid >> 5, lane = tid & 31;
    const int g = lane >> 2, t = lane & 3;
    const int wm = (WARPS_N == 2) ? (w >> 1) : w;
    const int wn = (WARPS_N == 2) ? (w & 1) : 0;
    const int row0 = blockIdx.x * BM;

    if (LAYER >= 0) {
        const float invN = 1.f / (float)N;
        for (int i = tid; i < K; i += 256) {
            float m = g_sum[LAYER][i] * invN;
            float var = g_sq[LAYER][i] * invN - m * m;
            mean_s[i] = m;
            r_s[i] = rsqrtf(var + 1e-5f);
        }
        __syncthreads();
    }

    float acc[MT][NT][4];
    #pragma unroll
    for (int mt = 0; mt < MT; mt++)
        #pragma unroll
        for (int nt = 0; nt < NT; nt++)
            #pragma unroll
            for (int q = 0; q < 4; q++) acc[mt][nt][q] = 0.f;

    float4 stA[NA], stW[NWL];

    // ---- staging helpers (lambdas via macros to keep reg names local) ----
    auto load_tile = [&](int kb) {
        #pragma unroll
        for (int p = 0; p < NA; p++) {
            int idx = p * 256 + tid;
            int r = idx >> 2;
            int kq = (idx & 3) * 4;
            int gr = row0 + r;
            float4 v = make_float4(0.f, 0.f, 0.f, 0.f);
            if (gr < N) {
                v = *(const float4*)(A + (size_t)gr * K + kb + kq);
                if (LAYER >= 0) {
                    int c = kb + kq;
                    v.x = (v.x - mean_s[c + 0]) * r_s[c + 0];
                    v.y = (v.y - mean_s[c + 1]) * r_s[c + 1];
                    v.z = (v.z - mean_s[c + 2]) * r_s[c + 2];
                    v.w = (v.w - mean_s[c + 3]) * r_s[c + 3];
                    *(float4*)(Hout + (size_t)gr * K + c) = v;
                }
            }
            stA[p] = v;
        }
        if (NW > 0) {
            #pragma unroll
            for (int p = 0; p < NW; p++) {
                int idx = p * 256 + tid;
                int k = idx / (OUT / 4);
                int nq = (idx % (OUT / 4)) * 4;
                stW[p] = *(const float4*)(W + (size_t)(kb + k) * OUT + nq);
            }
        } else {
            if (tid < (BK * OUT) / 4) {
                int k = tid / (OUT / 4);
                int nq = (tid % (OUT / 4)) * 4;
                stW[0] = *(const float4*)(W + (size_t)(kb + 0 + k) * OUT + nq);
            }
        }
    };
    auto store_tile = [&]() {
        #pragma unroll
        for (int p = 0; p < NA; p++) {
            int idx = p * 256 + tid;
            int r = idx >> 2;
            int kq = (idx & 3) * 4;
            float4 v = stA[p], h, l;
            tf32_split(v.x, h.x, l.x);
            tf32_split(v.y, h.y, l.y);
            tf32_split(v.z, h.z, l.z);
            tf32_split(v.w, h.w, l.w);
            *(float4*)&Ah[r][kq] = h;
            *(float4*)&Al[r][kq] = l;
        }
        if (NW > 0) {
            #pragma unroll
            for (int p = 0; p < NW; p++) {
                int idx = p * 256 + tid;
                int k = idx / (OUT / 4);
                int nq = (idx % (OUT / 4)) * 4;
                float4 v = stW[p], h, l;
                tf32_split(v.x, h.x, l.x);
                tf32_split(v.y, h.y, l.y);
                tf32_split(v.z, h.z, l.z);
                tf32_split(v.w, h.w, l.w);
                *(float4*)&Wh[k][nq] = h;
                *(float4*)&Wl[k][nq] = l;
            }
        } else {
            if (tid < (BK * OUT) / 4) {
                int k = tid / (OUT / 4);
                int nq = (tid % (OUT / 4)) * 4;
                float4 v = stW[0], h, l;
                tf32_split(v.x, h.x, l.x);
                tf32_split(v.y, h.y, l.y);
                tf32_split(v.z, h.z, l.z);
                tf32_split(v.w, h.w, l.w);
                *(float4*)&Wh[k][nq] = h;
                *(float4*)&Wl[k][nq] = l;
            }
        }
    };

    // Prologue: tile 0
    load_tile(0);
    store_tile();
    __syncthreads();

    for (int kb = 0; kb < K; kb += BK) {
        const bool last = (kb + BK >= K);
        if (!last) load_tile(kb + BK);     // prefetch next tile into registers

        #pragma unroll
        for (int ks = 0; ks < BK; ks += 8) {
            uint32_t ah[MT][4], al[MT][4];
            #pragma unroll
            for (int mt = 0; mt < MT; mt++) {
                int m = wm * WM + mt * 16 + g;
                ah[mt][0] = __float_as_uint(Ah[m][ks + t]);
                ah[mt][1] = __float_as_uint(Ah[m + 8][ks + t]);
                ah[mt][2] = __float_as_uint(Ah[m][ks + t + 4]);
                ah[mt][3] = __float_as_uint(Ah[m + 8][ks + t + 4]);
                al[mt][0] = __float_as_uint(Al[m][ks + t]);
                al[mt][1] = __float_as_uint(Al[m + 8][ks + t]);
                al[mt][2] = __float_as_uint(Al[m][ks + t + 4]);
                al[mt][3] = __float_as_uint(Al[m + 8][ks + t + 4]);
            }
            #pragma unroll
            for (int nt = 0; nt < NT; nt++) {
                int n = wn * WN + nt * 8 + g;
                uint32_t bh0 = __float_as_uint(Wh[ks + t][n]);
                uint32_t bh1 = __float_as_uint(Wh[ks + t + 4][n]);
                uint32_t bl0 = __float_as_uint(Wl[ks + t][n]);
                uint32_t bl1 = __float_as_uint(Wl[ks + t + 4][n]);
                #pragma unroll
                for (int mt = 0; mt < MT; mt++) {
                    mma_tf32(acc[mt][nt], ah[mt], bh0, bh1);  // hi*hi
                    mma_tf32(acc[mt][nt], ah[mt], bl0, bl1);  // hi*lo
                    mma_tf32(acc[mt][nt], al[mt], bh0, bh1);  // lo*hi
                }
            }
        }
        if (!last) {
            __syncthreads();
            store_tile();
            __syncthreads();
        }
    }

    // Epilogue: c0,c1 at (row, t*2), c2,c3 at (row+8, t*2)
    #pragma unroll
    for (int mt = 0; mt < MT; mt++) {
        int r0 = row0 + wm * WM + mt * 16 + g;
        #pragma unroll
        for (int nt = 0; nt < NT; nt++) {
            int n = wn * WN + nt * 8 + t * 2;
            if (r0 < N)
                *(float2*)(C + (size_t)r0 * OUT + n) =
                    make_float2(acc[mt][nt][0], acc[mt][nt][1]);
            if (r0 + 8 < N)
                *(float2*)(C + (size_t)(r0 + 8) * OUT + n) =
                    make_float2(acc[mt][nt][2], acc[mt][nt][3]);
        }
    }
}

// ---------------------------------------------------------------------------
// SpMM (warp per row, CSR) + leaky_relu + elu fused.
// Scalar 128B-coalesced gathers (cross-LDG wavefronts = 1.0 cyc/wf, vs 2.07
// for within-LDG.128 replays), 2-edge unroll for MLP.
// Block-local BN stat accumulation into g_sum/g_sq.
template<int OUT, int LAYER>
__global__ __launch_bounds__(256)
void spmm_kernel(const float* __restrict__ support,
                 const int* __restrict__ col,
                 const float* __restrict__ vals,
                 float* __restrict__ t, int N) {
    constexpr int J = OUT / 32;
    __shared__ float ssum[OUT], ssq[OUT];
    const int tid = threadIdx.x;
    for (int i = tid; i < OUT; i += blockDim.x) { ssum[i] = 0.f; ssq[i] = 0.f; }
    __syncthreads();

    const int lane = tid & 31;
    const int warp = tid >> 5;
    const int row = blockIdx.x * 8 + warp;

    if (row < N) {
        float acc[J];
        #pragma unroll
        for (int j = 0; j < J; j++) acc[j] = 0.f;

        const int s = g_rowptr[row];
        const int e = g_rowptr[row + 1];

        int i = s;
        for (; i + 2 <= e; i += 2) {
            int c0 = __ldg(&col[i]);
            int c1 = __ldg(&col[i + 1]);
            float v0 = __ldg(&vals[i]);
            float v1 = __ldg(&vals[i + 1]);
            const float* p0 = support + (size_t)c0 * OUT + lane;
            const float* p1 = support + (size_t)c1 * OUT + lane;
            float m0[J], m1[J];
            #pragma unroll
            for (int j = 0; j < J; j++) m0[j] = __ldg(p0 + 32 * j);
            #pragma unroll
            for (int j = 0; j < J; j++) m1[j] = __ldg(p1 + 32 * j);
            #pragma unroll
            for (int j = 0; j < J; j++)
                acc[j] = fmaf(v1, m1[j], fmaf(v0, m0[j], acc[j]));
        }
        if (i < e) {
            int c0 = __ldg(&col[i]);
            float v0 = __ldg(&vals[i]);
            const float* p0 = support + (size_t)c0 * OUT + lane;
            #pragma unroll
            for (int j = 0; j < J; j++)
                acc[j] = fmaf(v0, __ldg(p0 + 32 * j), acc[j]);
        }

        float* trow = t + (size_t)row * OUT + lane;
        #pragma unroll
        for (int j = 0; j < J; j++) {
            float a = acc[j];
            // leaky_relu(0.2) then elu; sign preserved -> single branch
            float tv = (a > 0.f) ? a : expm1f(0.2f * a);
            trow[32 * j] = tv;
            atomicAdd(&ssum[lane + 32 * j], tv);
            atomicAdd(&ssq[lane + 32 * j], tv * tv);
        }
    }
    __syncthreads();
    for (int i = tid; i < OUT; i += blockDim.x) {
        atomicAdd(&g_sum[LAYER][i], ssum[i]);
        atomicAdd(&g_sq[LAYER][i], ssq[i]);
    }
}

// ---------------------------------------------------------------------------
// BatchNorm (final layer only): out = (t - mean) * rsqrt(var + eps)
template<int OUT, int LAYER>
__global__ void norm_kernel(const float* __restrict__ t, float* __restrict__ out, int N) {
    __shared__ float mean_s[OUT], r_s[OUT];
    const float invN = 1.f / (float)N;
    for (int i = threadIdx.x; i < OUT; i += blockDim.x) {
        float m = g_sum[LAYER][i] * invN;
        float var = g_sq[LAYER][i] * invN - m * m;
        mean_s[i] = m;
        r_s[i] = rsqrtf(var + 1e-5f);
    }
    __syncthreads();
    const float4* t4 = (const float4*)t;
    float4* o4 = (float4*)out;
    size_t total4 = (size_t)N * OUT / 4;
    for (size_t i = (size_t)blockIdx.x * blockDim.x + threadIdx.x; i < total4;
         i += (size_t)gridDim.x * blockDim.x) {
        int cb = (int)(i & (OUT / 4 - 1)) * 4;
        float4 v = t4[i];
        float4 r;
        r.x = (v.x - mean_s[cb + 0]) * r_s[cb + 0];
        r.y = (v.y - mean_s[cb + 1]) * r_s[cb + 1];
        r.z = (v.z - mean_s[cb + 2]) * r_s[cb + 2];
        r.w = (v.w - mean_s[cb + 3]) * r_s[cb + 3];
        o4[i] = r;
    }
}

// ---------------------------------------------------------------------------
extern "C" void kernel_launch(void* const* d_in, const int* in_sizes, int n_in,
                              void* d_out, int out_size) {
    const float* x        = (const float*)d_in[0];
    const int*   adj_row  = (const int*)d_in[1];
    const int*   adj_col  = (const int*)d_in[2];
    const float* adj_vals = (const float*)d_in[3];
    const float* W1 = (const float*)d_in[4];
    const float* W2 = (const float*)d_in[5];
    const float* W3 = (const float*)d_in[6];
    const float* W4 = (const float*)d_in[7];
    float* out = (float*)d_out;

    const int N = in_sizes[0] / 256;
    const int E = in_sizes[1];

    float* g_support_p; cudaGetSymbolAddress((void**)&g_support_p, g_support);
    float* g_t_p;       cudaGetSymbolAddress((void**)&g_t_p, g_t);

    float* h1 = out;                       // [N,128]
    float* h2 = out + (size_t)N * 128;     // [N,128]
    float* h3 = out + (size_t)N * 256;     // [N,64]
    float* h4 = out + (size_t)N * 320;     // [N,32]

    zero_stats_kernel<<<1, 128>>>();
    rowptr_kernel<<<(N + 256) / 256, 256>>>(adj_row, N, E);

    const int gemm_blocks = (N + 127) / 128;
    const int spmm_blocks = (N + 7) / 8;
    const int norm_blocks = 1184;  // 8 * 148

    // Layer 1: support = x @ W1 ; t1 = act(spmm)
    gemm_tc<256, 128, -1><<<gemm_blocks, 256>>>(x, W1, g_support_p, nullptr, N);
    spmm_kernel<128, 0><<<spmm_blocks, 256>>>(g_support_p, adj_col, adj_vals, g_t_p, N);

    // Layer 2: GEMM reads t1, fuses BN(layer0): writes h1 AND support = h1 @ W2
    gemm_tc<128, 128, 0><<<gemm_blocks, 256>>>(g_t_p, W2, g_support_p, h1, N);
    spmm_kernel<128, 1><<<spmm_blocks, 256>>>(g_support_p, adj_col, adj_vals, g_t_p, N);

    // Layer 3: GEMM reads t2, fuses BN(layer1): writes h2 AND support = h2 @ W3
    gemm_tc<128, 64, 1><<<gemm_blocks, 256>>>(g_t_p, W3, g_support_p, h2, N);
    spmm_kernel<64, 2><<<spmm_blocks, 256>>>(g_support_p, adj_col, adj_vals, g_t_p, N);

    // Layer 4: GEMM reads t3, fuses BN(layer2): writes h3 AND support = h3 @ W4
    gemm_tc<64, 32, 2><<<gemm_blocks, 256>>>(g_t_p, W4, g_support_p, h3, N);
    spmm_kernel<32, 3><<<spmm_blocks, 256>>>(g_support_p, adj_col, adj_vals, g_t_p, N);

    // Final norm for h4
    norm_kernel<32, 3><<<norm_blocks, 256>>>(g_t_p, h4, N);
}

// round 8
// speedup vs baseline: 1.7862x; 1.0417x over previous
#include <cuda_runtime.h>
#include <cuda_fp16.h>
#include <math.h>
#include <stdint.h>

#define NMAX 100000
#define EMAX 1600000

// Scratch (allocation-free rule: __device__ globals)
__device__ __half g_support[(size_t)NMAX * 128];
__device__ float  g_t[(size_t)NMAX * 128];
__device__ float  g_sum[4][128];
__device__ float  g_sq[4][128];
__device__ int    g_rowptr[NMAX + 1];

// ---------------------------------------------------------------------------
__global__ void zero_stats_kernel() {
    int i = threadIdx.x;
    if (i < 128) {
        #pragma unroll
        for (int l = 0; l < 4; l++) { g_sum[l][i] = 0.f; g_sq[l][i] = 0.f; }
    }
}

// ---------------------------------------------------------------------------
// CSR row_ptr from sorted adj_row via binary search (lower_bound of r).
__global__ void rowptr_kernel(const int* __restrict__ adj_row, int N, int E) {
    int r = blockIdx.x * blockDim.x + threadIdx.x;
    if (r > N) return;
    int lo = 0, hi = E;
    while (lo < hi) {
        int mid = (lo + hi) >> 1;
        if (adj_row[mid] < r) lo = mid + 1; else hi = mid;
    }
    g_rowptr[r] = lo;
}

// ---------------------------------------------------------------------------
// tf32 helpers
__device__ __forceinline__ uint32_t f2tf32(float v) {
    uint32_t r;
    asm("cvt.rna.tf32.f32 %0, %1;" : "=r"(r) : "f"(v));
    return r;
}
__device__ __forceinline__ void tf32_split(float v, float& h, float& l) {
    uint32_t hu = f2tf32(v);
    h = __uint_as_float(hu);
    l = __uint_as_float(f2tf32(v - h));
}
__device__ __forceinline__ void mma_tf32(float c[4], const uint32_t a[4],
                                         uint32_t b0, uint32_t b1) {
    asm volatile(
        "mma.sync.aligned.m16n8k8.row.col.f32.tf32.tf32.f32 "
        "{%0,%1,%2,%3}, {%4,%5,%6,%7}, {%8,%9}, {%0,%1,%2,%3};\n"
        : "+f"(c[0]), "+f"(c[1]), "+f"(c[2]), "+f"(c[3])
        : "r"(a[0]), "r"(a[1]), "r"(a[2]), "r"(a[3]), "r"(b0), "r"(b1));
}

// ---------------------------------------------------------------------------
// Tensor-core tf32 GEMM (3xTF32 compensation), fused input-BatchNorm:
//   If LAYER >= 0: A is pre-norm t of layer LAYER; normalized on load using
//   that layer's global stats, normalized value written to Hout (fp32 d_out
//   slice) and fed to the mma.
// C[N,OUT] (fp16) = norm(A)[N,K] @ W[K,OUT]. BM=128, BK=16, 8 warps.
// Register-prefetch double buffering over the K loop.
template<int K, int OUT, int LAYER>
__global__ __launch_bounds__(256)
void gemm_tc(const float* __restrict__ A, const float* __restrict__ W,
             __half* __restrict__ C, float* __restrict__ Hout, int N) {
    constexpr int BM = 128, BK = 16;
    constexpr int AST = BK + 4;            // 20: g*20+t bijective mod 32 (conflict-free)
    constexpr int WST = OUT + 8;           // stride%32=8 -> t*8+g bijective
    constexpr int WARPS_M = (OUT >= 64) ? 4 : 8;
    constexpr int WARPS_N = 8 / WARPS_M;
    constexpr int WM = BM / WARPS_M;       // 32 or 16
    constexpr int WN = OUT / WARPS_N;      // 64 / 32 / 32
    constexpr int MT = WM / 16;            // 2 or 1
    constexpr int NT = WN / 8;             // 8 / 4 / 4
    constexpr int NA = (BM * BK) / (4 * 256);    // float4 A loads per thread = 2
    constexpr int NW = (BK * OUT) / (4 * 256);   // float4 W loads per thread (0 => partial)
    constexpr int NWL = (NW > 0) ? NW : 1;

    __shared__ float Ah[BM][AST], Al[BM][AST];
    __shared__ float Wh[BK][WST], Wl[BK][WST];
    __shared__ float mean_s[128], r_s[128];

    const int tid = threadIdx.x;
    const int w = tid >> 5, lane = tid & 31;
    const int g = lane >> 2, t = lane & 3;
    const int wm = (WARPS_N == 2) ? (w >> 1) : w;
    const int wn = (WARPS_N == 2) ? (w & 1) : 0;
    const int row0 = blockIdx.x * BM;

    if (LAYER >= 0) {
        const float invN = 1.f / (float)N;
        for (int i = tid; i < K; i += 256) {
            float m = g_sum[LAYER][i] * invN;
            float var = g_sq[LAYER][i] * invN - m * m;
            mean_s[i] = m;
            r_s[i] = rsqrtf(var + 1e-5f);
        }
        __syncthreads();
    }

    float acc[MT][NT][4];
    #pragma unroll
    for (int mt = 0; mt < MT; mt++)
        #pragma unroll
        for (int nt = 0; nt < NT; nt++)
            #pragma unroll
            for (int q = 0; q < 4; q++) acc[mt][nt][q] = 0.f;

    float4 stA[NA], stW[NWL];

    auto load_tile = [&](int kb) {
        #pragma unroll
        for (int p = 0; p < NA; p++) {
            int idx = p * 256 + tid;
            int r = idx >> 2;
            int kq = (idx & 3) * 4;
            int gr = row0 + r;
            float4 v = make_float4(0.f, 0.f, 0.f, 0.f);
            if (gr < N) {
                v = *(const float4*)(A + (size_t)gr * K + kb + kq);
                if (LAYER >= 0) {
                    int c = kb + kq;
                    v.x = (v.x - mean_s[c + 0]) * r_s[c + 0];
                    v.y = (v.y - mean_s[c + 1]) * r_s[c + 1];
                    v.z = (v.z - mean_s[c + 2]) * r_s[c + 2];
                    v.w = (v.w - mean_s[c + 3]) * r_s[c + 3];
                    *(float4*)(Hout + (size_t)gr * K + c) = v;
                }
            }
            stA[p] = v;
        }
        if (NW > 0) {
            #pragma unroll
            for (int p = 0; p < NW; p++) {
                int idx = p * 256 + tid;
                int k = idx / (OUT / 4);
                int nq = (idx % (OUT / 4)) * 4;
                stW[p] = *(const float4*)(W + (size_t)(kb + k) * OUT + nq);
            }
        } else {
            if (tid < (BK * OUT) / 4) {
                int k = tid / (OUT / 4);
                int nq = (tid % (OUT / 4)) * 4;
                stW[0] = *(const float4*)(W + (size_t)(kb + k) * OUT + nq);
            }
        }
    };
    auto store_tile = [&]() {
        #pragma unroll
        for (int p = 0; p < NA; p++) {
            int idx = p * 256 + tid;
            int r = idx >> 2;
            int kq = (idx & 3) * 4;
            float4 v = stA[p], h, l;
            tf32_split(v.x, h.x, l.x);
            tf32_split(v.y, h.y, l.y);
            tf32_split(v.z, h.z, l.z);
            tf32_split(v.w, h.w, l.w);
            *(float4*)&Ah[r][kq] = h;
            *(float4*)&Al[r][kq] = l;
        }
        if (NW > 0) {
            #pragma unroll
            for (int p = 0; p < NW; p++) {
                int idx = p * 256 + tid;
                int k = idx / (OUT / 4);
                int nq = (idx % (OUT / 4)) * 4;
                float4 v = stW[p], h, l;
                tf32_split(v.x, h.x, l.x);
                tf32_split(v.y, h.y, l.y);
                tf32_split(v.z, h.z, l.z);
                tf32_split(v.w, h.w, l.w);
                *(float4*)&Wh[k][nq] = h;
                *(float4*)&Wl[k][nq] = l;
            }
        } else {
            if (tid < (BK * OUT) / 4) {
                int k = tid / (OUT / 4);
                int nq = (tid % (OUT / 4)) * 4;
                float4 v = stW[0], h, l;
                tf32_split(v.x, h.x, l.x);
                tf32_split(v.y, h.y, l.y);
                tf32_split(v.z, h.z, l.z);
                tf32_split(v.w, h.w, l.w);
                *(float4*)&Wh[k][nq] = h;
                *(float4*)&Wl[k][nq] = l;
            }
        }
    };

    load_tile(0);
    store_tile();
    __syncthreads();

    for (int kb = 0; kb < K; kb += BK) {
        const bool last = (kb + BK >= K);
        if (!last) load_tile(kb + BK);     // prefetch next tile into registers

        #pragma unroll
        for (int ks = 0; ks < BK; ks += 8) {
            uint32_t ah[MT][4], al[MT][4];
            #pragma unroll
            for (int mt = 0; mt < MT; mt++) {
                int m = wm * WM + mt * 16 + g;
                ah[mt][0] = __float_as_uint(Ah[m][ks + t]);
                ah[mt][1] = __float_as_uint(Ah[m + 8][ks + t]);
                ah[mt][2] = __float_as_uint(Ah[m][ks + t + 4]);
                ah[mt][3] = __float_as_uint(Ah[m + 8][ks + t + 4]);
                al[mt][0] = __float_as_uint(Al[m][ks + t]);
                al[mt][1] = __float_as_uint(Al[m + 8][ks + t]);
                al[mt][2] = __float_as_uint(Al[m][ks + t + 4]);
                al[mt][3] = __float_as_uint(Al[m + 8][ks + t + 4]);
            }
            #pragma unroll
            for (int nt = 0; nt < NT; nt++) {
                int n = wn * WN + nt * 8 + g;
                uint32_t bh0 = __float_as_uint(Wh[ks + t][n]);
                uint32_t bh1 = __float_as_uint(Wh[ks + t + 4][n]);
                uint32_t bl0 = __float_as_uint(Wl[ks + t][n]);
                uint32_t bl1 = __float_as_uint(Wl[ks + t + 4][n]);
                #pragma unroll
                for (int mt = 0; mt < MT; mt++) {
                    mma_tf32(acc[mt][nt], ah[mt], bh0, bh1);  // hi*hi
                    mma_tf32(acc[mt][nt], ah[mt], bl0, bl1);  // hi*lo
                    mma_tf32(acc[mt][nt], al[mt], bh0, bh1);  // lo*hi
                }
            }
        }
        if (!last) {
            __syncthreads();
            store_tile();
            __syncthreads();
        }
    }

    // Epilogue -> fp16 support. c0,c1 at (row, t*2); c2,c3 at (row+8, t*2).
    #pragma unroll
    for (int mt = 0; mt < MT; mt++) {
        int r0 = row0 + wm * WM + mt * 16 + g;
        #pragma unroll
        for (int nt = 0; nt < NT; nt++) {
            int n = wn * WN + nt * 8 + t * 2;
            if (r0 < N)
                *(__half2*)(C + (size_t)r0 * OUT + n) =
                    __floats2half2_rn(acc[mt][nt][0], acc[mt][nt][1]);
            if (r0 + 8 < N)
                *(__half2*)(C + (size_t)(r0 + 8) * OUT + n) =
                    __floats2half2_rn(acc[mt][nt][2], acc[mt][nt][3]);
        }
    }
}

// ---------------------------------------------------------------------------
// SpMM (warp per row, CSR) over fp16 support + leaky_relu + elu fused.
// half2 coalesced gathers, 4-edge unroll for MLP, fp32 accumulation.
// Block-local BN stat accumulation into g_sum/g_sq.
template<int OUT, int LAYER>
__global__ __launch_bounds__(256)
void spmm_kernel(const __half* __restrict__ support,
                 const int* __restrict__ col,
                 const float* __restrict__ vals,
                 float* __restrict__ t, int N) {
    constexpr int H2 = (OUT >= 64) ? OUT / 64 : 0;   // half2 loads/lane: 2,1,0
    constexpr int JF = (OUT >= 64) ? 2 * H2 : 1;     // fp32 outputs/lane: 4,2,1
    __shared__ float ssum[OUT], ssq[OUT];
    const int tid = threadIdx.x;
    for (int i = tid; i < OUT; i += blockDim.x) { ssum[i] = 0.f; ssq[i] = 0.f; }
    __syncthreads();

    const int lane = tid & 31;
    const int warp = tid >> 5;
    const int row = blockIdx.x * 8 + warp;

    if (row < N) {
        float acc[JF];
        #pragma unroll
        for (int j = 0; j < JF; j++) acc[j] = 0.f;

        const int s = g_rowptr[row];
        const int e = g_rowptr[row + 1];

        auto gather1 = [&](int i) {
            int c = __ldg(&col[i]);
            float v = __ldg(&vals[i]);
            const __half* p = support + (size_t)c * OUT;
            if constexpr (H2 >= 1) {
                #pragma unroll
                for (int h = 0; h < H2; h++) {
                    __half2 m = __ldg((const __half2*)p + h * 32 + lane);
                    float2 f = __half22float2(m);
                    acc[2 * h + 0] = fmaf(v, f.x, acc[2 * h + 0]);
                    acc[2 * h + 1] = fmaf(v, f.y, acc[2 * h + 1]);
                }
            } else {
                acc[0] = fmaf(v, __half2float(__ldg(p + lane)), acc[0]);
            }
        };

        int i = s;
        for (; i + 4 <= e; i += 4) {
            int c0 = __ldg(&col[i]),     c1 = __ldg(&col[i + 1]);
            int c2 = __ldg(&col[i + 2]), c3 = __ldg(&col[i + 3]);
            float v0 = __ldg(&vals[i]),     v1 = __ldg(&vals[i + 1]);
            float v2 = __ldg(&vals[i + 2]), v3 = __ldg(&vals[i + 3]);
            const __half* p0 = support + (size_t)c0 * OUT;
            const __half* p1 = support + (size_t)c1 * OUT;
            const __half* p2 = support + (size_t)c2 * OUT;
            const __half* p3 = support + (size_t)c3 * OUT;
            if constexpr (H2 >= 1) {
                __half2 m0[H2], m1[H2], m2[H2], m3[H2];
                #pragma unroll
                for (int h = 0; h < H2; h++) m0[h] = __ldg((const __half2*)p0 + h * 32 + lane);
                #pragma unroll
                for (int h = 0; h < H2; h++) m1[h] = __ldg((const __half2*)p1 + h * 32 + lane);
                #pragma unroll
                for (int h = 0; h < H2; h++) m2[h] = __ldg((const __half2*)p2 + h * 32 + lane);
                #pragma unroll
                for (int h = 0; h < H2; h++) m3[h] = __ldg((const __half2*)p3 + h * 32 + lane);
                #pragma unroll
                for (int h = 0; h < H2; h++) {
                    float2 f0 = __half22float2(m0[h]);
                    float2 f1 = __half22float2(m1[h]);
                    float2 f2 = __half22float2(m2[h]);
                    float2 f3 = __half22float2(m3[h]);
                    acc[2*h+0] = fmaf(v3, f3.x, fmaf(v2, f2.x, fmaf(v1, f1.x, fmaf(v0, f0.x, acc[2*h+0]))));
                    acc[2*h+1] = fmaf(v3, f3.y, fmaf(v2, f2.y, fmaf(v1, f1.y, fmaf(v0, f0.y, acc[2*h+1]))));
                }
            } else {
                float f0 = __half2float(__ldg(p0 + lane));
                float f1 = __half2float(__ldg(p1 + lane));
                float f2 = __half2float(__ldg(p2 + lane));
                float f3 = __half2float(__ldg(p3 + lane));
                acc[0] = fmaf(v3, f3, fmaf(v2, f2, fmaf(v1, f1, fmaf(v0, f0, acc[0]))));
            }
        }
        for (; i < e; i++) gather1(i);

        // leaky_relu(0.2) then elu; sign preserved -> single branch
        float tv[JF];
        #pragma unroll
        for (int j = 0; j < JF; j++) {
            float a = acc[j];
            tv[j] = (a > 0.f) ? a : expm1f(0.2f * a);
        }

        float* trow = t + (size_t)row * OUT;
        if constexpr (H2 >= 1) {
            #pragma unroll
            for (int h = 0; h < H2; h++) {
                int c = 64 * h + 2 * lane;
                *(float2*)(trow + c) = make_float2(tv[2*h+0], tv[2*h+1]);
                atomicAdd(&ssum[c + 0], tv[2*h+0]);
                atomicAdd(&ssum[c + 1], tv[2*h+1]);
                atomicAdd(&ssq[c + 0], tv[2*h+0] * tv[2*h+0]);
                atomicAdd(&ssq[c + 1], tv[2*h+1] * tv[2*h+1]);
            }
        } else {
            trow[lane] = tv[0];
            atomicAdd(&ssum[lane], tv[0]);
            atomicAdd(&ssq[lane], tv[0] * tv[0]);
        }
    }
    __syncthreads();
    for (int i = tid; i < OUT; i += blockDim.x) {
        atomicAdd(&g_sum[LAYER][i], ssum[i]);
        atomicAdd(&g_sq[LAYER][i], ssq[i]);
    }
}

// ---------------------------------------------------------------------------
// BatchNorm (final layer only): out = (t - mean) * rsqrt(var + eps)
template<int OUT, int LAYER>
__global__ void norm_kernel(const float* __restrict__ t, float* __restrict__ out, int N) {
    __shared__ float mean_s[OUT], r_s[OUT];
    const float invN = 1.f / (float)N;
    for (int i = threadIdx.x; i < OUT; i += blockDim.x) {
        float m = g_sum[LAYER][i] * invN;
        float var = g_sq[LAYER][i] * invN - m * m;
        mean_s[i] = m;
        r_s[i] = rsqrtf(var + 1e-5f);
    }
    __syncthreads();
    const float4* t4 = (const float4*)t;
    float4* o4 = (float4*)out;
    size_t total4 = (size_t)N * OUT / 4;
    for (size_t i = (size_t)blockIdx.x * blockDim.x + threadIdx.x; i < total4;
         i += (size_t)gridDim.x * blockDim.x) {
        int cb = (int)(i & (OUT / 4 - 1)) * 4;
        float4 v = t4[i];
        float4 r;
        r.x = (v.x - mean_s[cb + 0]) * r_s[cb + 0];
        r.y = (v.y - mean_s[cb + 1]) * r_s[cb + 1];
        r.z = (v.z - mean_s[cb + 2]) * r_s[cb + 2];
        r.w = (v.w - mean_s[cb + 3]) * r_s[cb + 3];
        o4[i] = r;
    }
}

// ---------------------------------------------------------------------------
extern "C" void kernel_launch(void* const* d_in, const int* in_sizes, int n_in,
                              void* d_out, int out_size) {
    const float* x        = (const float*)d_in[0];
    const int*   adj_row  = (const int*)d_in[1];
    const int*   adj_col  = (const int*)d_in[2];
    const float* adj_vals = (const float*)d_in[3];
    const float* W1 = (const float*)d_in[4];
    const float* W2 = (const float*)d_in[5];
    const float* W3 = (const float*)d_in[6];
    const float* W4 = (const float*)d_in[7];
    float* out = (float*)d_out;

    const int N = in_sizes[0] / 256;
    const int E = in_sizes[1];

    __half* g_support_p; cudaGetSymbolAddress((void**)&g_support_p, g_support);
    float*  g_t_p;       cudaGetSymbolAddress((void**)&g_t_p, g_t);

    float* h1 = out;                       // [N,128]
    float* h2 = out + (size_t)N * 128;     // [N,128]
    float* h3 = out + (size_t)N * 256;     // [N,64]
    float* h4 = out + (size_t)N * 320;     // [N,32]

    zero_stats_kernel<<<1, 128>>>();
    rowptr_kernel<<<(N + 256) / 256, 256>>>(adj_row, N, E);

    const int gemm_blocks = (N + 127) / 128;
    const int spmm_blocks = (N + 7) / 8;
    const int norm_blocks = 1184;  // 8 * 148

    // Layer 1: support = x @ W1 ; t1 = act(spmm)
    gemm_tc<256, 128, -1><<<gemm_blocks, 256>>>(x, W1, g_support_p, nullptr, N);
    spmm_kernel<128, 0><<<spmm_blocks, 256>>>(g_support_p, adj_col, adj_vals, g_t_p, N);

    // Layer 2: GEMM reads t1, fuses BN(layer0): writes h1 AND support = h1 @ W2
    gemm_tc<128, 128, 0><<<gemm_blocks, 256>>>(g_t_p, W2, g_support_p, h1, N);
    spmm_kernel<128, 1><<<spmm_blocks, 256>>>(g_support_p, adj_col, adj_vals, g_t_p, N);

    // Layer 3: GEMM reads t2, fuses BN(layer1): writes h2 AND support = h2 @ W3
    gemm_tc<128, 64, 1><<<gemm_blocks, 256>>>(g_t_p, W3, g_support_p, h2, N);
    spmm_kernel<64, 2><<<spmm_blocks, 256>>>(g_support_p, adj_col, adj_vals, g_t_p, N);

    // Layer 4: GEMM reads t3, fuses BN(layer2): writes h3 AND support = h3 @ W4
    gemm_tc<64, 32, 2><<<gemm_blocks, 256>>>(g_t_p, W4, g_support_p, h3, N);
    spmm_kernel<32, 3><<<spmm_blocks, 256>>>(g_support_p, adj_col, adj_vals, g_t_p, N);

    // Final norm for h4
    norm_kernel<32, 3><<<norm_blocks, 256>>>(g_t_p, h4, N);
}